// round 4
// baseline (speedup 1.0000x reference)
#include <cuda_runtime.h>
#include <cstdint>
#include <cstddef>

#define TT 512
#define BB 64
#define HH 512
#define GH 1024  // 2*H

// ---------------------------------------------------------------------------
// Scratch (__device__ globals: no allocations allowed)
// ---------------------------------------------------------------------------
__device__ float g_G[2][(size_t)TT * BB * GH];  // gate preacts x@Wih^T + b
__device__ float g_Z[2][(size_t)TT * BB * HH];  // tanh(x@Wc^T)
__device__ float g_C[2][BB * HH];               // running cell state

// ---------------------------------------------------------------------------
// Packed f32x2 helpers (Blackwell)
// ---------------------------------------------------------------------------
__device__ __forceinline__ unsigned long long pk2(float x, float y) {
    unsigned long long r;
    asm("mov.b64 %0, {%1, %2};" : "=l"(r) : "f"(x), "f"(y));
    return r;
}
__device__ __forceinline__ void upk2(unsigned long long v, float& x, float& y) {
    asm("mov.b64 {%0, %1}, %2;" : "=f"(x), "=f"(y) : "l"(v));
}
__device__ __forceinline__ void fma2(unsigned long long& d, unsigned long long a,
                                     unsigned long long b) {
    asm("fma.rn.f32x2 %0, %1, %2, %0;" : "+l"(d) : "l"(a), "l"(b));
}

// ---------------------------------------------------------------------------
// Precompute GEMM: C[M,N] = X[M,512] @ W[N,512]^T (+bias | tanh)
// BM=BN=128, BK=16, 256 threads, 8x8 microtile via f32x2.
// grid = (N/128, M/128)
// ---------------------------------------------------------------------------
__global__ __launch_bounds__(256, 2)
void gemm_xwt(const float* __restrict__ X, const float* __restrict__ W,
              const float* __restrict__ bias, float* __restrict__ C,
              int N, int act)
{
    __shared__ float Xs[16][132];
    __shared__ float Ws[16][132];

    const int tid = threadIdx.x;
    const int bm = blockIdx.y * 128;
    const int bn = blockIdx.x * 128;
    const int tx = tid & 15;        // col group (8 cols each)
    const int ty = tid >> 4;        // row group (8 rows each)
    const int lr = tid >> 2;        // 0..63 load row
    const int lk = (tid & 3) << 2;  // 0,4,8,12 load k-offset

    unsigned long long acc[8][4];
#pragma unroll
    for (int i = 0; i < 8; ++i)
#pragma unroll
        for (int j = 0; j < 4; ++j) acc[i][j] = 0ull;

    const float* Xp = X + (size_t)(bm + lr) * 512 + lk;
    const float* Wp = W + (size_t)(bn + lr) * 512 + lk;

    for (int kt = 0; kt < 32; ++kt) {
        const int ko = kt * 16;
        float4 xa = *(const float4*)(Xp + ko);
        float4 xb = *(const float4*)(Xp + ko + (size_t)64 * 512);
        float4 wa = *(const float4*)(Wp + ko);
        float4 wb = *(const float4*)(Wp + ko + (size_t)64 * 512);

        __syncthreads();  // previous tile's compute done
        Xs[lk + 0][lr] = xa.x; Xs[lk + 1][lr] = xa.y;
        Xs[lk + 2][lr] = xa.z; Xs[lk + 3][lr] = xa.w;
        Xs[lk + 0][lr + 64] = xb.x; Xs[lk + 1][lr + 64] = xb.y;
        Xs[lk + 2][lr + 64] = xb.z; Xs[lk + 3][lr + 64] = xb.w;
        Ws[lk + 0][lr] = wa.x; Ws[lk + 1][lr] = wa.y;
        Ws[lk + 2][lr] = wa.z; Ws[lk + 3][lr] = wa.w;
        Ws[lk + 0][lr + 64] = wb.x; Ws[lk + 1][lr + 64] = wb.y;
        Ws[lk + 2][lr + 64] = wb.z; Ws[lk + 3][lr + 64] = wb.w;
        __syncthreads();

#pragma unroll
        for (int kk = 0; kk < 16; ++kk) {
            float4 a0 = *(const float4*)&Xs[kk][ty * 8];
            float4 a1 = *(const float4*)&Xs[kk][ty * 8 + 4];
            float4 b0 = *(const float4*)&Ws[kk][tx * 8];
            float4 b1 = *(const float4*)&Ws[kk][tx * 8 + 4];
            unsigned long long bp[4];
            bp[0] = pk2(b0.x, b0.y); bp[1] = pk2(b0.z, b0.w);
            bp[2] = pk2(b1.x, b1.y); bp[3] = pk2(b1.z, b1.w);
            float av[8] = {a0.x, a0.y, a0.z, a0.w, a1.x, a1.y, a1.z, a1.w};
#pragma unroll
            for (int i = 0; i < 8; ++i) {
                unsigned long long ap = pk2(av[i], av[i]);
#pragma unroll
                for (int j = 0; j < 4; ++j) fma2(acc[i][j], ap, bp[j]);
            }
        }
    }

    // epilogue
    float bv[8];
    if (act == 0) {
#pragma unroll
        for (int j = 0; j < 8; ++j) bv[j] = bias[bn + tx * 8 + j];
    }
#pragma unroll
    for (int i = 0; i < 8; ++i) {
        float v[8];
#pragma unroll
        for (int j = 0; j < 4; ++j) upk2(acc[i][j], v[2 * j], v[2 * j + 1]);
        if (act == 0) {
#pragma unroll
            for (int j = 0; j < 8; ++j) v[j] += bv[j];
        } else {
#pragma unroll
            for (int j = 0; j < 8; ++j) v[j] = tanhf(v[j]);
        }
        float* cp = C + (size_t)(bm + ty * 8 + i) * N + bn + tx * 8;
        *(float4*)(cp)     = make_float4(v[0], v[1], v[2], v[3]);
        *(float4*)(cp + 4) = make_float4(v[4], v[5], v[6], v[7]);
    }
}

// ---------------------------------------------------------------------------
// One scan step, both directions. 128 blocks = 2 dirs x 64 tiles (8 gate pairs).
// Per block: A[64,16] = h_prev @ Whh^T over 16 gate rows (f cols j0..j0+7 and
// o cols 512+j0..+7), then fused cell update + residual output.
// h_prev is read from the output tensor itself (the residual output IS h).
// ---------------------------------------------------------------------------
__global__ __launch_bounds__(256)
void step_kernel(const float* __restrict__ xin,
                 const float* __restrict__ Whh_f, const float* __restrict__ Whh_b,
                 const float* __restrict__ h0f, const float* __restrict__ h0b,
                 float* __restrict__ out, int s)
{
    __shared__ float Hs[32][68];  // [k][row] transposed h chunk
    __shared__ float Ws[32][17];  // [k][col] weight chunk
    __shared__ float P[64][17];   // GEMM result tile

    const int tid = threadIdx.x;
    const int d = blockIdx.x >> 6;      // 0 = fwd, 1 = bwd
    const int tile = blockIdx.x & 63;
    const int j0 = tile * 8;

    const int ts = d ? (TT - 1 - s) : s;
    const float* Whh = d ? Whh_b : Whh_f;
    const float* hp;
    int hstride;
    if (s == 0) {
        hp = d ? h0b : h0f;
        hstride = HH;
    } else {
        const int pts = d ? ts + 1 : ts - 1;
        hp = out + (size_t)pts * BB * GH + (size_t)d * HH;
        hstride = GH;
    }

    // compute roles: 2 k-slices x 16 row-groups x 8 col-groups
    const int ks = tid >> 7;
    const int t2 = tid & 127;
    const int rg = t2 >> 3;  // 0..15 -> rows rg*4..+3
    const int cg = t2 & 7;   // 0..7  -> cols cg*2, cg*2+1

    // load roles
    const int lr = tid & 63;   // H row
    const int lkg = tid >> 6;  // 0..3 -> k offsets lkg*8 .. +7
    const int wc = tid >> 3;   // 0..15 (only tid<128)
    const int wk = (tid & 7) * 4;

    unsigned long long acc[2][2];
    acc[0][0] = acc[0][1] = acc[1][0] = acc[1][1] = 0ull;

    for (int kt = 0; kt < 16; ++kt) {
        const int k0 = kt * 32;
        float4 h1 = *(const float4*)(hp + (size_t)lr * hstride + k0 + lkg * 8);
        float4 h2 = *(const float4*)(hp + (size_t)lr * hstride + k0 + lkg * 8 + 4);
        float4 wv = make_float4(0.f, 0.f, 0.f, 0.f);
        if (tid < 128) {
            const int grow = (wc < 8) ? (j0 + wc) : (HH + j0 + wc - 8);
            wv = *(const float4*)(Whh + (size_t)grow * HH + k0 + wk);
        }
        __syncthreads();
        Hs[lkg * 8 + 0][lr] = h1.x; Hs[lkg * 8 + 1][lr] = h1.y;
        Hs[lkg * 8 + 2][lr] = h1.z; Hs[lkg * 8 + 3][lr] = h1.w;
        Hs[lkg * 8 + 4][lr] = h2.x; Hs[lkg * 8 + 5][lr] = h2.y;
        Hs[lkg * 8 + 6][lr] = h2.z; Hs[lkg * 8 + 7][lr] = h2.w;
        if (tid < 128) {
            Ws[wk + 0][wc] = wv.x; Ws[wk + 1][wc] = wv.y;
            Ws[wk + 2][wc] = wv.z; Ws[wk + 3][wc] = wv.w;
        }
        __syncthreads();

        if ((kt >> 3) == ks) {
#pragma unroll
            for (int kk = 0; kk < 32; ++kk) {
                float4 hv = *(const float4*)&Hs[kk][rg * 4];
                float w0 = Ws[kk][cg * 2];
                float w1 = Ws[kk][cg * 2 + 1];
                unsigned long long ha = pk2(hv.x, hv.y);
                unsigned long long hb = pk2(hv.z, hv.w);
                unsigned long long w0p = pk2(w0, w0);
                unsigned long long w1p = pk2(w1, w1);
                fma2(acc[0][0], ha, w0p);
                fma2(acc[1][0], hb, w0p);
                fma2(acc[0][1], ha, w1p);
                fma2(acc[1][1], hb, w1p);
            }
        }
    }
    __syncthreads();

    // split-K reduction through smem
    if (ks == 0) {
#pragma unroll
        for (int rp = 0; rp < 2; ++rp)
#pragma unroll
            for (int c = 0; c < 2; ++c) {
                float lo, hi;
                upk2(acc[rp][c], lo, hi);
                P[rg * 4 + rp * 2 + 0][cg * 2 + c] = lo;
                P[rg * 4 + rp * 2 + 1][cg * 2 + c] = hi;
            }
    }
    __syncthreads();
    if (ks == 1) {
#pragma unroll
        for (int rp = 0; rp < 2; ++rp)
#pragma unroll
            for (int c = 0; c < 2; ++c) {
                float lo, hi;
                upk2(acc[rp][c], lo, hi);
                P[rg * 4 + rp * 2 + 0][cg * 2 + c] += lo;
                P[rg * 4 + rp * 2 + 1][cg * 2 + c] += hi;
            }
    }
    __syncthreads();

    // fused elementwise: gates -> cell -> residual output
    const float* G = g_G[d];
    const float* Z = g_Z[d];
    float* Cs = g_C[d];
    const size_t rowbase = (size_t)ts * BB;
    for (int e = tid; e < 512; e += 256) {
        const int r = e >> 3;
        const int p = e & 7;
        const int col = j0 + p;
        const size_t gi = (rowbase + r) * GH;
        const float af = P[r][p] + G[gi + col];
        const float ao = P[r][8 + p] + G[gi + HH + col];
        const float f = 1.f / (1.f + expf(-af));
        const float o = 1.f / (1.f + expf(-ao));
        const size_t zi = (rowbase + r) * HH + col;
        const int ci = r * HH + col;
        const float c = f * Cs[ci] + (1.f - f) * Z[zi];
        Cs[ci] = c;
        const float ov = o * tanhf(c) + (1.f - o) * xin[zi];
        out[gi + (size_t)d * HH + col] = ov;
    }
}

// ---------------------------------------------------------------------------
__global__ void init_c(const float* __restrict__ cf, const float* __restrict__ cb) {
    const int i = blockIdx.x * blockDim.x + threadIdx.x;
    if (i < BB * HH) {
        g_C[0][i] = cf[i];
        g_C[1][i] = cb[i];
    }
}

__global__ void finalize(float* __restrict__ out) {
    const int i = blockIdx.x * blockDim.x + threadIdx.x;
    if (i >= BB * HH) return;
    const int r = i >> 9;
    const int c = i & 511;
    float* dst = out + (size_t)TT * BB * GH;
    dst[i] = out[(size_t)(TT - 1) * BB * GH + (size_t)r * GH + c];  // h_fwd final
    dst[BB * HH + i] = g_C[0][i];                                    // c_fwd final
    dst[2 * BB * HH + i] = out[(size_t)r * GH + HH + c];             // h_bwd final
    dst[3 * BB * HH + i] = g_C[1][i];                                // c_bwd final
}

// ---------------------------------------------------------------------------
extern "C" void kernel_launch(void* const* d_in, const int* in_sizes, int n_in,
                              void* d_out, int out_size) {
    const float* x    = (const float*)d_in[0];
    const float* h0f  = (const float*)d_in[1];
    const float* c0f  = (const float*)d_in[2];
    const float* h0b  = (const float*)d_in[3];
    const float* c0b  = (const float*)d_in[4];
    const float* Wihf = (const float*)d_in[5];
    const float* Whhf = (const float*)d_in[6];
    const float* bf   = (const float*)d_in[7];
    const float* Wcf  = (const float*)d_in[8];
    const float* Wihb = (const float*)d_in[9];
    const float* Whhb = (const float*)d_in[10];
    const float* bb   = (const float*)d_in[11];
    const float* Wcb  = (const float*)d_in[12];
    float* out = (float*)d_out;

    void* pG = nullptr;
    void* pZ = nullptr;
    cudaGetSymbolAddress(&pG, g_G);
    cudaGetSymbolAddress(&pZ, g_Z);
    float* G = (float*)pG;
    float* Z = (float*)pZ;
    const size_t GSTRIDE = (size_t)TT * BB * GH;
    const size_t ZSTRIDE = (size_t)TT * BB * HH;

    init_c<<<64, 512>>>(c0f, c0b);

    gemm_xwt<<<dim3(8, 256), 256>>>(x, Wihf, bf, G, GH, 0);
    gemm_xwt<<<dim3(8, 256), 256>>>(x, Wihb, bb, G + GSTRIDE, GH, 0);
    gemm_xwt<<<dim3(4, 256), 256>>>(x, Wcf, nullptr, Z, HH, 1);
    gemm_xwt<<<dim3(4, 256), 256>>>(x, Wcb, nullptr, Z + ZSTRIDE, HH, 1);

    for (int s = 0; s < TT; ++s) {
        step_kernel<<<128, 256>>>(x, Whhf, Whhb, h0f, h0b, out, s);
    }

    if ((size_t)out_size >= (size_t)TT * BB * GH + 4u * (size_t)BB * HH) {
        finalize<<<64, 512>>>(out);
    }
}

// round 5
// speedup vs baseline: 1.0758x; 1.0758x over previous
#include <cuda_runtime.h>
#include <cstdint>
#include <cstddef>

#define TT 512
#define BB 64
#define HH 512
#define GH 1024  // 2*H
#define NB 128   // persistent grid size

typedef unsigned long long ull;

// ---------------------------------------------------------------------------
// Scratch (__device__ globals: no allocations allowed)
// ---------------------------------------------------------------------------
__device__ float g_G[2][(size_t)TT * BB * GH];  // gate preacts x@Wih^T + b
__device__ float g_Z[2][(size_t)TT * BB * HH];  // tanh(x@Wc^T)
__device__ float g_C[2][BB * HH];               // final cell state
__device__ int g_count = 0;
__device__ volatile int g_gen = 0;

// ---------------------------------------------------------------------------
// Packed f32x2 helpers (Blackwell)
// ---------------------------------------------------------------------------
__device__ __forceinline__ ull pk2(float x, float y) {
    ull r;
    asm("mov.b64 %0, {%1, %2};" : "=l"(r) : "f"(x), "f"(y));
    return r;
}
__device__ __forceinline__ void upk2(ull v, float& x, float& y) {
    asm("mov.b64 {%0, %1}, %2;" : "=f"(x), "=f"(y) : "l"(v));
}
__device__ __forceinline__ void fma2(ull& d, ull a, ull b) {
    asm("fma.rn.f32x2 %0, %1, %2, %0;" : "+l"(d) : "l"(a), "l"(b));
}

__device__ __forceinline__ float sig_f(float x) {
    return __fdividef(1.f, 1.f + __expf(-x));
}
__device__ __forceinline__ float tanh_f(float x) {
    return fmaf(-2.f, __fdividef(1.f, __expf(2.f * x) + 1.f), 1.f);
}

// ---------------------------------------------------------------------------
// Precompute GEMM: C[M,N] = X[M,512] @ W[N,512]^T (+bias | tanhf)
// BM=BN=128, BK=16, 256 threads, 8x8 microtile, f32x2, mov-free inner loop.
// ---------------------------------------------------------------------------
__global__ __launch_bounds__(256, 2)
void gemm_xwt(const float* __restrict__ X, const float* __restrict__ W,
              const float* __restrict__ bias, float* __restrict__ C,
              int N, int act)
{
    __shared__ ull   Xsd[16][128];   // duplicated (x,x) pairs, 16KB
    __shared__ float Ws[16][132];    // plain weights, pairs read via LDS

    const int tid = threadIdx.x;
    const int bm = blockIdx.y * 128;
    const int bn = blockIdx.x * 128;
    const int tx = tid & 15;        // col group (8 cols)
    const int ty = tid >> 4;        // row group (8 rows)
    const int lr = tid >> 2;        // 0..63 load row
    const int lk = (tid & 3) << 2;  // 0,4,8,12 load k-offset

    ull acc[8][4];
#pragma unroll
    for (int i = 0; i < 8; ++i)
#pragma unroll
        for (int j = 0; j < 4; ++j) acc[i][j] = 0ull;

    const float* Xp = X + (size_t)(bm + lr) * 512 + lk;
    const float* Wp = W + (size_t)(bn + lr) * 512 + lk;

    for (int kt = 0; kt < 32; ++kt) {
        const int ko = kt * 16;
        float4 xa = *(const float4*)(Xp + ko);
        float4 xb = *(const float4*)(Xp + ko + (size_t)64 * 512);
        float4 wa = *(const float4*)(Wp + ko);
        float4 wb = *(const float4*)(Wp + ko + (size_t)64 * 512);

        __syncthreads();
        Xsd[lk + 0][lr] = pk2(xa.x, xa.x); Xsd[lk + 1][lr] = pk2(xa.y, xa.y);
        Xsd[lk + 2][lr] = pk2(xa.z, xa.z); Xsd[lk + 3][lr] = pk2(xa.w, xa.w);
        Xsd[lk + 0][lr + 64] = pk2(xb.x, xb.x); Xsd[lk + 1][lr + 64] = pk2(xb.y, xb.y);
        Xsd[lk + 2][lr + 64] = pk2(xb.z, xb.z); Xsd[lk + 3][lr + 64] = pk2(xb.w, xb.w);
        Ws[lk + 0][lr] = wa.x; Ws[lk + 1][lr] = wa.y;
        Ws[lk + 2][lr] = wa.z; Ws[lk + 3][lr] = wa.w;
        Ws[lk + 0][lr + 64] = wb.x; Ws[lk + 1][lr + 64] = wb.y;
        Ws[lk + 2][lr + 64] = wb.z; Ws[lk + 3][lr + 64] = wb.w;
        __syncthreads();

#pragma unroll
        for (int kk = 0; kk < 16; ++kk) {
            const ull* xr = &Xsd[kk][ty * 8];
            ulonglong2 a01 = *(const ulonglong2*)(xr + 0);
            ulonglong2 a23 = *(const ulonglong2*)(xr + 2);
            ulonglong2 a45 = *(const ulonglong2*)(xr + 4);
            ulonglong2 a67 = *(const ulonglong2*)(xr + 6);
            const float* wr = &Ws[kk][tx * 8];
            ulonglong2 b01 = *(const ulonglong2*)(wr);
            ulonglong2 b23 = *(const ulonglong2*)(wr + 4);
            ull ap[8] = {a01.x, a01.y, a23.x, a23.y, a45.x, a45.y, a67.x, a67.y};
            ull bp[4] = {b01.x, b01.y, b23.x, b23.y};
#pragma unroll
            for (int i = 0; i < 8; ++i)
#pragma unroll
                for (int j = 0; j < 4; ++j) fma2(acc[i][j], ap[i], bp[j]);
        }
    }

    float bv[8];
    if (act == 0) {
#pragma unroll
        for (int j = 0; j < 8; ++j) bv[j] = bias[bn + tx * 8 + j];
    }
#pragma unroll
    for (int i = 0; i < 8; ++i) {
        float v[8];
#pragma unroll
        for (int j = 0; j < 4; ++j) upk2(acc[i][j], v[2 * j], v[2 * j + 1]);
        if (act == 0) {
#pragma unroll
            for (int j = 0; j < 8; ++j) v[j] += bv[j];
        } else {
#pragma unroll
            for (int j = 0; j < 8; ++j) v[j] = tanhf(v[j]);
        }
        float* cp = C + (size_t)(bm + ty * 8 + i) * N + bn + tx * 8;
        *(float4*)(cp)     = make_float4(v[0], v[1], v[2], v[3]);
        *(float4*)(cp + 4) = make_float4(v[4], v[5], v[6], v[7]);
    }
}

// ---------------------------------------------------------------------------
// Grid barrier (sense-reversal on generation counter). All NB CTAs resident.
// ---------------------------------------------------------------------------
__device__ __forceinline__ void grid_barrier() {
    __syncthreads();
    if (threadIdx.x == 0) {
        __threadfence();
        int gen = g_gen;
        if (atomicAdd(&g_count, 1) == NB - 1) {
            g_count = 0;
            __threadfence();
            g_gen = gen + 1;
        } else {
            while (g_gen == gen) { }
        }
        __threadfence();
    }
    __syncthreads();
}

// ---------------------------------------------------------------------------
// Persistent scan kernel. 128 CTAs = 2 dirs x 64 col-tiles (8 cols each).
// Per CTA: Whh slice resident in smem (duplicated u64 pairs), c in registers,
// h chained through `out`. One grid barrier per step.
// smem: Wd 64KB | Hs double-buffer 32KB (P overlays Hs buf0).
// ---------------------------------------------------------------------------
__global__ __launch_bounds__(256, 1)
void regu_scan(const float* __restrict__ x,
               const float* __restrict__ Whh_f, const float* __restrict__ Whh_b,
               const float* __restrict__ h0f, const float* __restrict__ h0b,
               const float* __restrict__ c0f, const float* __restrict__ c0b,
               float* __restrict__ out)
{
    extern __shared__ char sm_raw[];
    ull*   Wd = (ull*)sm_raw;                 // [512][16] duplicated pairs
    float* Hs = (float*)(sm_raw + 65536);     // [2][64 k][64 b]
    float* P  = (float*)(sm_raw + 65536);     // [64][17] overlays Hs buf0

    const int tid  = threadIdx.x;
    const int d    = blockIdx.x >> 6;
    const int tile = blockIdx.x & 63;
    const int j0   = tile * 8;

    // GEMM compute roles: warp = gate pair, lane = batch pair
    const int rg = tid & 31;
    const int gp = tid >> 5;
    const int g0 = 2 * gp, g1 = 2 * gp + 1;

    // elementwise roles: 2 cells (b, j0+ep), (b, j0+ep+1)
    const int eb = tid >> 2;
    const int ep = (tid & 3) * 2;

    // staging roles
    const int sb  = tid & 63;
    const int skg = tid >> 6;  // 0..3 -> k sub-offsets

    const float* Whh = d ? Whh_b : Whh_f;
    const float* h0  = d ? h0b : h0f;
    const float* c0s = d ? c0b : c0f;
    const float* G   = g_G[d];
    const float* Z   = g_Z[d];

    // Preload Whh slice, duplicated (w,w)
    for (int idx = tid; idx < 16 * 512; idx += 256) {
        const int g = idx >> 9, k = idx & 511;
        const int grow = (g < 8) ? (j0 + g) : (HH + j0 + (g - 8));
        const float w = Whh[(size_t)grow * HH + k];
        Wd[k * 16 + g] = pk2(w, w);
    }

    float2 creg = *(const float2*)(c0s + (size_t)eb * HH + j0 + ep);
    __syncthreads();

    for (int s = 0; s < TT; ++s) {
        if (s > 0) grid_barrier();

        const int t = d ? (TT - 1 - s) : s;
        const float* hsrc;
        int hstride;
        if (s == 0) {
            hsrc = h0; hstride = HH;
        } else {
            const int pt = d ? (t + 1) : (t - 1);
            hsrc = out + (size_t)pt * BB * GH + (size_t)d * HH;
            hstride = GH;
        }

        // prefetch elementwise operands (independent of h -> latency hidden)
        const size_t rowi = (size_t)t * BB + eb;
        const float2 gf = *(const float2*)(G + rowi * GH + j0 + ep);
        const float2 go = *(const float2*)(G + rowi * GH + HH + j0 + ep);
        const float2 zf = *(const float2*)(Z + rowi * HH + j0 + ep);
        const float2 xf = *(const float2*)(x + rowi * HH + j0 + ep);

        ull acc0 = 0ull, acc1 = 0ull;

        const float* hb = hsrc + (size_t)sb * hstride;
        float4 rr0 = *(const float4*)(hb + skg * 16 + 0);
        float4 rr1 = *(const float4*)(hb + skg * 16 + 4);
        float4 rr2 = *(const float4*)(hb + skg * 16 + 8);
        float4 rr3 = *(const float4*)(hb + skg * 16 + 12);

        for (int kt = 0; kt < 8; ++kt) {
            float* Hbuf = Hs + (kt & 1) * 4096;
            float* dstS = Hbuf + (skg * 16) * 64 + sb;
            dstS[0 * 64]  = rr0.x; dstS[1 * 64]  = rr0.y; dstS[2 * 64]  = rr0.z; dstS[3 * 64]  = rr0.w;
            dstS[4 * 64]  = rr1.x; dstS[5 * 64]  = rr1.y; dstS[6 * 64]  = rr1.z; dstS[7 * 64]  = rr1.w;
            dstS[8 * 64]  = rr2.x; dstS[9 * 64]  = rr2.y; dstS[10 * 64] = rr2.z; dstS[11 * 64] = rr2.w;
            dstS[12 * 64] = rr3.x; dstS[13 * 64] = rr3.y; dstS[14 * 64] = rr3.z; dstS[15 * 64] = rr3.w;
            __syncthreads();
            if (kt < 7) {
                const float* src = hb + (kt + 1) * 64 + skg * 16;
                rr0 = *(const float4*)(src + 0);
                rr1 = *(const float4*)(src + 4);
                rr2 = *(const float4*)(src + 8);
                rr3 = *(const float4*)(src + 12);
            }
            const float* Hp = Hbuf + 2 * rg;
            const ull* Wk = Wd + kt * 64 * 16;
#pragma unroll 16
            for (int kk = 0; kk < 64; ++kk) {
                const ull hv = *(const ull*)(Hp + kk * 64);
                fma2(acc0, hv, Wk[kk * 16 + g0]);
                fma2(acc1, hv, Wk[kk * 16 + g1]);
            }
        }
        __syncthreads();

        // write GEMM tile to P
        {
            float lo, hi;
            upk2(acc0, lo, hi);
            P[(2 * rg) * 17 + g0] = lo; P[(2 * rg + 1) * 17 + g0] = hi;
            upk2(acc1, lo, hi);
            P[(2 * rg) * 17 + g1] = lo; P[(2 * rg + 1) * 17 + g1] = hi;
        }
        __syncthreads();

        // fused elementwise: gates -> cell -> residual output (h)
        const float pf0 = P[eb * 17 + ep],     pf1 = P[eb * 17 + ep + 1];
        const float po0 = P[eb * 17 + 8 + ep], po1 = P[eb * 17 + 8 + ep + 1];
        const float f0 = sig_f(pf0 + gf.x), f1 = sig_f(pf1 + gf.y);
        const float o0 = sig_f(po0 + go.x), o1 = sig_f(po1 + go.y);
        const float cn0 = f0 * creg.x + (1.f - f0) * zf.x;
        const float cn1 = f1 * creg.y + (1.f - f1) * zf.y;
        creg.x = cn0; creg.y = cn1;
        float2 hv2;
        hv2.x = o0 * tanh_f(cn0) + (1.f - o0) * xf.x;
        hv2.y = o1 * tanh_f(cn1) + (1.f - o1) * xf.y;
        *(float2*)(out + rowi * GH + (size_t)d * HH + j0 + ep) = hv2;
    }

    // final cell state
    *(float2*)(&g_C[d][eb * HH + j0 + ep]) = creg;
}

// ---------------------------------------------------------------------------
__global__ void finalize(float* __restrict__ out) {
    const int i = blockIdx.x * blockDim.x + threadIdx.x;
    if (i >= BB * HH) return;
    const int r = i >> 9;
    const int c = i & 511;
    float* dst = out + (size_t)TT * BB * GH;
    dst[i] = out[(size_t)(TT - 1) * BB * GH + (size_t)r * GH + c];  // h_fwd final
    dst[BB * HH + i] = g_C[0][i];                                    // c_fwd final
    dst[2 * BB * HH + i] = out[(size_t)r * GH + HH + c];             // h_bwd final
    dst[3 * BB * HH + i] = g_C[1][i];                                // c_bwd final
}

// ---------------------------------------------------------------------------
extern "C" void kernel_launch(void* const* d_in, const int* in_sizes, int n_in,
                              void* d_out, int out_size) {
    const float* x    = (const float*)d_in[0];
    const float* h0f  = (const float*)d_in[1];
    const float* c0f  = (const float*)d_in[2];
    const float* h0b  = (const float*)d_in[3];
    const float* c0b  = (const float*)d_in[4];
    const float* Wihf = (const float*)d_in[5];
    const float* Whhf = (const float*)d_in[6];
    const float* bf   = (const float*)d_in[7];
    const float* Wcf  = (const float*)d_in[8];
    const float* Wihb = (const float*)d_in[9];
    const float* Whhb = (const float*)d_in[10];
    const float* bb   = (const float*)d_in[11];
    const float* Wcb  = (const float*)d_in[12];
    float* out = (float*)d_out;

    void* pG = nullptr;
    void* pZ = nullptr;
    cudaGetSymbolAddress(&pG, g_G);
    cudaGetSymbolAddress(&pZ, g_Z);
    float* G = (float*)pG;
    float* Z = (float*)pZ;
    const size_t GSTRIDE = (size_t)TT * BB * GH;
    const size_t ZSTRIDE = (size_t)TT * BB * HH;

    gemm_xwt<<<dim3(8, 256), 256>>>(x, Wihf, bf, G, GH, 0);
    gemm_xwt<<<dim3(8, 256), 256>>>(x, Wihb, bb, G + GSTRIDE, GH, 0);
    gemm_xwt<<<dim3(4, 256), 256>>>(x, Wcf, nullptr, Z, HH, 1);
    gemm_xwt<<<dim3(4, 256), 256>>>(x, Wcb, nullptr, Z + ZSTRIDE, HH, 1);

    const int smem = 65536 + 32768;  // Wd + Hs double buffer
    cudaFuncSetAttribute(regu_scan, cudaFuncAttributeMaxDynamicSharedMemorySize, smem);
    regu_scan<<<NB, 256, smem>>>(x, Whhf, Whhb, h0f, h0b, c0f, c0b, out);

    if ((size_t)out_size >= (size_t)TT * BB * GH + 4u * (size_t)BB * HH) {
        finalize<<<64, 512>>>(out);
    }
}